// round 16
// baseline (speedup 1.0000x reference)
#include <cuda_runtime.h>
#include <cuda_fp16.h>
#include <math.h>
#include <stdint.h>

// Problem dims (fixed)
#define Bv 32
#define Sv 1024
#define Dv 1024
#define Av 256
#define Ev 16
#define Mrows (Bv * Sv)   // 32768

// ---------------------------------------------------------------------------
// Persistent scratch (no cudaMalloc allowed)
// ---------------------------------------------------------------------------
__device__ __half g_h2[(size_t)Mrows * Av];          // stage1+2 out fp16
__device__ __half g_uo[(size_t)Mrows * Dv];          // up-proj out fp16
__device__ __half g_dwh[Av * Dv];                    // down_W fp16
__device__ __half g_uwh[Dv * Av];                    // up_W fp16
__device__ __half g_ewh[Ev * Av * Av];               // expert_W fp16
__device__ int g_idx[Bv];
__device__ int g_valid[Bv];

// ---------------------------------------------------------------------------
__device__ __forceinline__ uint32_t smem_u32(const void* p) {
    uint32_t a;
    asm("{ .reg .u64 t; cvta.to.shared.u64 t, %1; cvt.u32.u64 %0, t; }" : "=r"(a) : "l"(p));
    return a;
}
#define LDSM4(r, addr) \
    asm volatile("ldmatrix.sync.aligned.m8n8.x4.shared.b16 {%0,%1,%2,%3}, [%4];" \
        : "=r"((r)[0]), "=r"((r)[1]), "=r"((r)[2]), "=r"((r)[3]) : "r"(addr))
#define MMA_OP(d, a, b0, b1) \
    asm volatile("mma.sync.aligned.m16n8k16.row.col.f32.f16.f16.f32 " \
        "{%0,%1,%2,%3}, {%4,%5,%6,%7}, {%8,%9}, {%0,%1,%2,%3};" \
        : "+f"((d)[0]), "+f"((d)[1]), "+f"((d)[2]), "+f"((d)[3]) \
        : "r"((a)[0]), "r"((a)[1]), "r"((a)[2]), "r"((a)[3]), "r"(b0), "r"(b1))
#define CP16(dst, src) \
    asm volatile("cp.async.cg.shared.global [%0], [%1], 16;" :: "r"(dst), "l"(src))
#define CPCOMMIT() asm volatile("cp.async.commit_group;" ::: "memory")
#define CPWAIT0()  asm volatile("cp.async.wait_group 0;" ::: "memory")
#define CPWAIT1()  asm volatile("cp.async.wait_group 1;" ::: "memory")

// ---- fused_s12 SMEM layout (256 threads, 64 rows/block) ----
#define FA_OFF 0u
#define FB_OFF 8192u
#define FSTAGE 40960u                  // A 8K + B 32K
#define H1F_OFF (2u * FSTAGE)          // 81920: h1 tile 64x256, 4 chunks x 8KB
#define SMEM_FUSED (H1F_OFF + 32768u)  // 114688

// ---- hmma_s3 SMEM layout (256 threads, 128x128 tile, 3-stage) ----
#define SA_OFF 0u
#define SB_OFF 16384u
#define SSTAGE 32768u                  // A 16K + B 16K
#define SMEM_S3 (3u * SSTAGE)          // 98304

// ---------------------------------------------------------------------------
// conv_all + domain-id prep in one launch.
// ---------------------------------------------------------------------------
__global__ void conv_all(const float* __restrict__ dw, __half* __restrict__ DW,
                         const float* __restrict__ uw, __half* __restrict__ UW,
                         const float* __restrict__ ew, __half* __restrict__ EW,
                         const int* __restrict__ dom) {
    if (blockIdx.x == 0 && threadIdx.x == 0) {
        bool is64 = true;
        for (int k = 0; k < 16; k++) {
            int hi = dom[2 * k + 1];
            if (hi != 0 && hi != -1) { is64 = false; break; }
        }
        for (int b = 0; b < Bv; b++) {
            long long v;
            if (is64) {
                unsigned int lo = (unsigned int)dom[2 * b];
                int hi = dom[2 * b + 1];
                v = ((long long)hi << 32) | (long long)lo;
            } else {
                v = dom[b];
            }
            g_valid[b] = (v >= 0 && v < Ev) ? 1 : 0;
            long long c = v < 0 ? 0 : (v > (Ev - 1) ? (Ev - 1) : v);
            g_idx[b] = (int)c;
        }
    }
    const int n_dw = Av * Dv / 4, n_uw = Dv * Av / 4, n_ew = Ev * Av * Av / 4;
    const int total = n_dw + n_uw + n_ew;
    for (int i = blockIdx.x * blockDim.x + threadIdx.x; i < total;
         i += gridDim.x * blockDim.x) {
        const float* src;
        __half* dst;
        int j = i;
        if (j < n_dw) { src = dw; dst = DW; }
        else if ((j -= n_dw) < n_uw) { src = uw; dst = UW; }
        else { j -= n_uw; src = ew; dst = EW; }
        float4 v = ((const float4*)src)[j];
        __half2 h0 = __floats2half2_rn(v.x, v.y);
        __half2 h1 = __floats2half2_rn(v.z, v.w);
        ((uint2*)dst)[j] = make_uint2(*(uint32_t*)&h0, *(uint32_t*)&h1);
    }
}

__device__ __forceinline__ float gelu_exact(float v) {
    return 0.5f * v * (1.0f + erff(v * 0.70710678118654752440f));
}

__device__ __forceinline__ void conv_store(char* base, uint32_t off, float4 v) {
    __half2 h0 = __floats2half2_rn(v.x, v.y);
    __half2 h1 = __floats2half2_rn(v.z, v.w);
    *(uint2*)(base + off) = make_uint2(*(uint32_t*)&h0, *(uint32_t*)&h1);
}

// cp.async loaders into swizzled SMEM (256 threads).
template <int ROWS>
__device__ __forceinline__ void load_t(uint32_t dst,
                                       const __half* __restrict__ hi,
                                       int tid, int K, int k0) {
#pragma unroll
    for (int i = 0; i < ROWS / 32; i++) {
        const int idx = tid + i * 256;
        const int row = idx >> 3;
        const int c8 = idx & 7;
        const uint32_t off = (uint32_t)(row * 128) +
                             (uint32_t)((c8 * 16) ^ ((row & 7) << 4));
        CP16(dst + off, hi + (size_t)row * K + k0 + c8 * 8);
    }
}

// Warp-tile compute step (warp tile 32x64: mt 2, nt 8).
__device__ __forceinline__ void k16_step(uint32_t aBase, uint32_t bBase,
                                         int wm, int wn, int lane, int k16,
                                         float acc[2][8][4]) {
    uint32_t ah[2][4], bh[4][4];
#pragma unroll
    for (int mt = 0; mt < 2; mt++) {
        const int row = wm * 32 + mt * 16 + (lane & 15);
        const int kc  = k16 * 16 + (lane >> 4) * 8;
        const uint32_t off = (uint32_t)(row * 128) +
                             (uint32_t)((kc * 2) ^ ((row & 7) << 4));
        LDSM4(ah[mt], aBase + off);
    }
#pragma unroll
    for (int p = 0; p < 4; p++) {
        const int g    = lane >> 3;
        const int nrow = wn * 64 + p * 16 + (g >> 1) * 8 + (lane & 7);
        const int kc   = k16 * 16 + (g & 1) * 8;
        const uint32_t off = (uint32_t)(nrow * 128) +
                             (uint32_t)((kc * 2) ^ ((nrow & 7) << 4));
        LDSM4(bh[p], bBase + off);
    }
#pragma unroll
    for (int mt = 0; mt < 2; mt++)
#pragma unroll
        for (int nt = 0; nt < 8; nt++) {
            const int p = nt >> 1;
            const int q = (nt & 1) * 2;
            MMA_OP(acc[mt][nt], ah[mt], bh[p][q], bh[p][q + 1]);
        }
}

// h1 SMEM tile address (64-row chunks of 8KB): chunk = col/64.
__device__ __forceinline__ uint32_t h1f_off(int rl, int col) {
    return H1F_OFF + (uint32_t)((col >> 6) * 8192) + (uint32_t)(rl * 128) +
           (uint32_t)(((col & 63) * 2) ^ ((rl & 7) << 4));
}

// ---------------------------------------------------------------------------
// Fused stages 1+2: block = 64 rows x A=256, 256 threads (8 warps 2Mx4N).
// One __syncthreads per chunk (double-buffer invariant: stage s's last reader
// finished before the mid-sync of the previous chunk).
// ---------------------------------------------------------------------------
__global__ __launch_bounds__(256, 2)
void fused_s12(const float* __restrict__ Afp,
               const float* __restrict__ down_b,
               const float* __restrict__ expert_b,
               const float* __restrict__ domain_emb) {
    constexpr int K1 = Dv;
    constexpr int NC1 = K1 / 64;

    extern __shared__ char sm[];
    const uint32_t sbase = smem_u32(sm);

    const int tid  = threadIdx.x;
    const int lane = tid & 31;
    const int wid  = tid >> 5;
    const int wm   = wid & 1;
    const int wn   = wid >> 1;

    const int m0 = blockIdx.y * 64;
    const int b  = m0 >> 10;
    const int e  = g_idx[b];
    const int valid = g_valid[b];

    const float* ArowF = Afp + (size_t)m0 * K1;
    const __half* Brow2 = g_ewh + (size_t)e * Av * Av;
    const float* biasp = expert_b + (size_t)e * Av;
    const float* embp  = domain_emb + (size_t)e * Av;

    int lr[4], lc[4];
    uint32_t soff[4];
    float4 pA[4];
#pragma unroll
    for (int i = 0; i < 4; i++) {
        const int idx = tid + i * 256;
        lr[i] = idx >> 4;
        lc[i] = (idx & 15) * 4;
        soff[i] = (uint32_t)(lr[i] * 128) +
                  (uint32_t)((lc[i] * 2) ^ ((lr[i] & 7) << 4));
        pA[i] = *(const float4*)(ArowF + (size_t)lr[i] * K1 + lc[i]);
    }

    load_t<256>(sbase + FB_OFF, g_dwh, tid, K1, 0);
    CPCOMMIT();

    float acc[2][8][4];
#pragma unroll
    for (int mt = 0; mt < 2; mt++)
#pragma unroll
        for (int nt = 0; nt < 8; nt++)
#pragma unroll
            for (int q = 0; q < 4; q++) acc[mt][nt][q] = 0.f;

    // GEMM1 (K=1024) — single sync per chunk
    for (int c = 0; c < NC1; c++) {
        const int s = c & 1;
        const uint32_t sb = sbase + s * FSTAGE;
        char* smc = sm + s * FSTAGE;
#pragma unroll
        for (int i = 0; i < 4; i++)
            conv_store(smc + FA_OFF, soff[i], pA[i]);
        CPWAIT0();
        __syncthreads();

        if (c + 1 < NC1) {
            load_t<256>(sbase + ((s ^ 1) * FSTAGE) + FB_OFF, g_dwh, tid, K1, (c + 1) * 64);
            CPCOMMIT();
#pragma unroll
            for (int i = 0; i < 4; i++)
                pA[i] = *(const float4*)(ArowF + (size_t)lr[i] * K1 + (c + 1) * 64 + lc[i]);
        }
#pragma unroll
        for (int k16 = 0; k16 < 4; k16++)
            k16_step(sb + FA_OFF, sb + FB_OFF, wm, wn, lane, k16, acc);
    }
    __syncthreads();   // all GEMM1 compute done before H1 writes

    // epilogue 1: bias + GELU -> h1 in SMEM
#pragma unroll
    for (int mt = 0; mt < 2; mt++)
#pragma unroll
        for (int half = 0; half < 2; half++) {
            const int rl = wm * 32 + mt * 16 + (lane >> 2) + half * 8;
#pragma unroll
            for (int nt = 0; nt < 8; nt++) {
                const int col = wn * 64 + nt * 8 + (lane & 3) * 2;
                const float2 bi = *(const float2*)(down_b + col);
                float vx = gelu_exact(acc[mt][nt][half * 2] + bi.x);
                float vy = gelu_exact(acc[mt][nt][half * 2 + 1] + bi.y);
                __half2 h = __floats2half2_rn(vx, vy);
                *(uint32_t*)(sm + h1f_off(rl, col)) = *(uint32_t*)&h;
            }
        }
    __syncthreads();

    // GEMM2 (K=256, A = h1 in SMEM) — single sync per chunk
#pragma unroll
    for (int mt = 0; mt < 2; mt++)
#pragma unroll
        for (int nt = 0; nt < 8; nt++)
#pragma unroll
            for (int q = 0; q < 4; q++) acc[mt][nt][q] = 0.f;

    load_t<256>(sbase + FB_OFF, Brow2, tid, Av, 0);
    CPCOMMIT();

    for (int c = 0; c < 4; c++) {
        const int s = c & 1;
        const uint32_t sb = sbase + s * FSTAGE;
        CPWAIT0();
        __syncthreads();
        if (c + 1 < 4) {
            load_t<256>(sbase + ((s ^ 1) * FSTAGE) + FB_OFF, Brow2, tid, Av, (c + 1) * 64);
            CPCOMMIT();
        }
#pragma unroll
        for (int k16 = 0; k16 < 4; k16++)
            k16_step(sbase + H1F_OFF + (uint32_t)(c * 8192), sb + FB_OFF,
                     wm, wn, lane, k16, acc);
    }

    // epilogue 2: (+b_e or passthrough) + emb -> g_h2 fp16
    // (h1 reads below are per-thread-owned fragments; no barrier needed since
    //  H1 is read-only after epilogue 1.)
#pragma unroll
    for (int mt = 0; mt < 2; mt++)
#pragma unroll
        for (int half = 0; half < 2; half++) {
            const int rl = wm * 32 + mt * 16 + (lane >> 2) + half * 8;
            const int r  = m0 + rl;
#pragma unroll
            for (int nt = 0; nt < 8; nt++) {
                const int col = wn * 64 + nt * 8 + (lane & 3) * 2;
                float vx, vy;
                if (valid) {
                    const float2 bi = *(const float2*)(biasp + col);
                    vx = acc[mt][nt][half * 2] + bi.x;
                    vy = acc[mt][nt][half * 2 + 1] + bi.y;
                } else {
                    uint32_t ph = *(uint32_t*)(sm + h1f_off(rl, col));
                    float2 fh = __half22float2(*(__half2*)&ph);
                    vx = fh.x; vy = fh.y;
                }
                const float2 em = *(const float2*)(embp + col);
                vx += em.x; vy += em.y;
                __half2 h = __floats2half2_rn(vx, vy);
                *(uint32_t*)(g_h2 + (size_t)r * Av + col) = *(uint32_t*)&h;
            }
        }
}

// ---------------------------------------------------------------------------
// Stage 3: U = h2 * up_W^T + up_b -> g_uo fp16.
// 128x128 tile, 256 threads (8 warps 4Mx2N), 3-stage ring, 2 CTAs/SM.
// ---------------------------------------------------------------------------
__global__ __launch_bounds__(256, 2)
void hmma_s3(const float* __restrict__ bias) {
    constexpr int K = Av;
    constexpr int NC = K / 64;

    extern __shared__ char sm[];
    const uint32_t sbase = smem_u32(sm);

    const int tid  = threadIdx.x;
    const int lane = tid & 31;
    const int wid  = tid >> 5;
    const int wm   = wid & 3;
    const int wn   = wid >> 2;

    const int m0 = blockIdx.y * 128;
    const int n0 = blockIdx.x * 128;
    const __half* ArowH = g_h2 + (size_t)m0 * K;
    const __half* BrowH = g_uwh + (size_t)n0 * K;

    load_t<128>(sbase + SA_OFF, ArowH, tid, K, 0);
    load_t<128>(sbase + SB_OFF, BrowH, tid, K, 0);
    CPCOMMIT();
    load_t<128>(sbase + SSTAGE + SA_OFF, ArowH, tid, K, 64);
    load_t<128>(sbase + SSTAGE + SB_OFF, BrowH, tid, K, 64);
    CPCOMMIT();

    float acc[2][8][4];
#pragma unroll
    for (int mt = 0; mt < 2; mt++)
#pragma unroll
        for (int nt = 0; nt < 8; nt++)
#pragma unroll
            for (int q = 0; q < 4; q++) acc[mt][nt][q] = 0.f;

#pragma unroll
    for (int c = 0; c < NC; c++) {
        if (c < NC - 1) { CPWAIT1(); } else { CPWAIT0(); }
        __syncthreads();
        if (c + 2 < NC) {
            const uint32_t nb = sbase + ((c + 2) % 3) * SSTAGE;
            load_t<128>(nb + SA_OFF, ArowH, tid, K, (c + 2) * 64);
            load_t<128>(nb + SB_OFF, BrowH, tid, K, (c + 2) * 64);
            CPCOMMIT();
        }
        const uint32_t sb = sbase + (c % 3) * SSTAGE;
#pragma unroll
        for (int k16 = 0; k16 < 4; k16++)
            k16_step(sb + SA_OFF, sb + SB_OFF, wm, wn, lane, k16, acc);
    }

#pragma unroll
    for (int mt = 0; mt < 2; mt++)
#pragma unroll
        for (int half = 0; half < 2; half++) {
            const int r = m0 + wm * 32 + mt * 16 + (lane >> 2) + half * 8;
#pragma unroll
            for (int nt = 0; nt < 8; nt++) {
                const int col = n0 + wn * 64 + nt * 8 + (lane & 3) * 2;
                const float2 bi = *(const float2*)(bias + col);
                float vx = acc[mt][nt][half * 2] + bi.x;
                float vy = acc[mt][nt][half * 2 + 1] + bi.y;
                __half2 h = __floats2half2_rn(vx, vy);
                *(uint32_t*)(g_uo + (size_t)r * Dv + col) = *(uint32_t*)&h;
            }
        }
}

// ---------------------------------------------------------------------------
// LayerNorm: 128 threads/row, 8 elems/thread, coalesced.
// Cache policy: g_uo -> last-use (L2-resident from s3), residual/out -> streaming.
// ---------------------------------------------------------------------------
__global__ __launch_bounds__(128)
void ln_kernel(const float* __restrict__ residual,
               const float* __restrict__ gamma,
               const float* __restrict__ beta,
               float* __restrict__ out) {
    const int row = blockIdx.x;
    const int t = threadIdx.x;
    const int c0 = t * 8;

    const uint4 uh = __ldlu((const uint4*)(g_uo + (size_t)row * Dv + c0));
    const float4 r0 = __ldcs((const float4*)(residual + (size_t)row * Dv + c0));
    const float4 r1 = __ldcs((const float4*)(residual + (size_t)row * Dv + c0 + 4));

    float v[8];
    {
        float2 a = __half22float2(*(const __half2*)&uh.x);
        float2 b = __half22float2(*(const __half2*)&uh.y);
        float2 c = __half22float2(*(const __half2*)&uh.z);
        float2 d = __half22float2(*(const __half2*)&uh.w);
        v[0] = a.x + r0.x; v[1] = a.y + r0.y;
        v[2] = b.x + r0.z; v[3] = b.y + r0.w;
        v[4] = c.x + r1.x; v[5] = c.y + r1.y;
        v[6] = d.x + r1.z; v[7] = d.y + r1.w;
    }

    __shared__ float red1[4];
    __shared__ float red2[4];

    float s = 0.f;
#pragma unroll
    for (int i = 0; i < 8; i++) s += v[i];
#pragma unroll
    for (int o = 16; o; o >>= 1) s += __shfl_xor_sync(0xFFFFFFFFu, s, o);
    if ((t & 31) == 0) red1[t >> 5] = s;
    __syncthreads();
    const float mu = (red1[0] + red1[1] + red1[2] + red1[3]) * (1.0f / Dv);

    float s2 = 0.f;
#pragma unroll
    for (int i = 0; i < 8; i++) {
        v[i] -= mu;
        s2 += v[i] * v[i];
    }
#pragma unroll
    for (int o = 16; o; o >>= 1) s2 += __shfl_xor_sync(0xFFFFFFFFu, s2, o);
    if ((t & 31) == 0) red2[t >> 5] = s2;
    __syncthreads();
    const float inv = rsqrtf((red2[0] + red2[1] + red2[2] + red2[3]) * (1.0f / Dv) + 1e-5f);

    const float4 gm0 = *(const float4*)(gamma + c0);
    const float4 gm1 = *(const float4*)(gamma + c0 + 4);
    const float4 bt0 = *(const float4*)(beta + c0);
    const float4 bt1 = *(const float4*)(beta + c0 + 4);
    float4 o0, o1;
    o0.x = v[0] * inv * gm0.x + bt0.x;
    o0.y = v[1] * inv * gm0.y + bt0.y;
    o0.z = v[2] * inv * gm0.z + bt0.z;
    o0.w = v[3] * inv * gm0.w + bt0.w;
    o1.x = v[4] * inv * gm1.x + bt1.x;
    o1.y = v[5] * inv * gm1.y + bt1.y;
    o1.z = v[6] * inv * gm1.z + bt1.z;
    o1.w = v[7] * inv * gm1.w + bt1.w;
    __stcs((float4*)(out + (size_t)row * Dv + c0), o0);
    __stcs((float4*)(out + (size_t)row * Dv + c0 + 4), o1);
}

// ---------------------------------------------------------------------------
extern "C" void kernel_launch(void* const* d_in, const int* in_sizes, int n_in,
                              void* d_out, int out_size) {
    const float* hidden     = (const float*)d_in[0];
    const int*   dom        = (const int*)d_in[1];
    const float* down_W     = (const float*)d_in[2];
    const float* down_b     = (const float*)d_in[3];
    const float* up_W       = (const float*)d_in[4];
    const float* up_b       = (const float*)d_in[5];
    const float* expert_W   = (const float*)d_in[6];
    const float* expert_b   = (const float*)d_in[7];
    const float* domain_emb = (const float*)d_in[8];
    const float* gamma      = (const float*)d_in[9];
    const float* beta       = (const float*)d_in[10];
    float* out = (float*)d_out;

    cudaFuncSetAttribute(fused_s12, cudaFuncAttributeMaxDynamicSharedMemorySize, SMEM_FUSED);
    cudaFuncSetAttribute(hmma_s3, cudaFuncAttributeMaxDynamicSharedMemorySize, SMEM_S3);

    __half *dwh, *uwh, *ewh;
    cudaGetSymbolAddress((void**)&dwh, g_dwh);
    cudaGetSymbolAddress((void**)&uwh, g_uwh);
    cudaGetSymbolAddress((void**)&ewh, g_ewh);
    conv_all<<<512, 512>>>(down_W, dwh, up_W, uwh, expert_W, ewh, dom);

    // Stages 1+2 fused (64 rows/block, 2 CTAs/SM)
    fused_s12<<<dim3(1, Mrows / 64), 256, SMEM_FUSED>>>(hidden, down_b, expert_b, domain_emb);
    // Stage 3 (128x128 blocks, 2 CTAs/SM, 3-stage ring)
    hmma_s3<<<dim3(Dv / 128, Mrows / 128), 256, SMEM_S3>>>(up_b);
    // Residual + LayerNorm (coalesced, 128 thr/row)
    ln_kernel<<<Mrows, 128>>>(hidden, gamma, beta, out);
}

// round 17
// speedup vs baseline: 1.0132x; 1.0132x over previous
#include <cuda_runtime.h>
#include <cuda_fp16.h>
#include <math.h>
#include <stdint.h>

// Problem dims (fixed)
#define Bv 32
#define Sv 1024
#define Dv 1024
#define Av 256
#define Ev 16
#define Mrows (Bv * Sv)   // 32768

// ---------------------------------------------------------------------------
// Persistent scratch (no cudaMalloc allowed)
// ---------------------------------------------------------------------------
__device__ __half g_h2[(size_t)Mrows * Av];          // stage1+2 out fp16
__device__ __half g_uo[(size_t)Mrows * Dv];          // up-proj out fp16
__device__ __half g_dwh[Av * Dv];                    // down_W fp16
__device__ __half g_uwh[Dv * Av];                    // up_W fp16
__device__ __half g_ewh[Ev * Av * Av];               // expert_W fp16
__device__ int g_idx[Bv];
__device__ int g_valid[Bv];

// ---------------------------------------------------------------------------
__device__ __forceinline__ uint32_t smem_u32(const void* p) {
    uint32_t a;
    asm("{ .reg .u64 t; cvta.to.shared.u64 t, %1; cvt.u32.u64 %0, t; }" : "=r"(a) : "l"(p));
    return a;
}
#define LDSM4(r, addr) \
    asm volatile("ldmatrix.sync.aligned.m8n8.x4.shared.b16 {%0,%1,%2,%3}, [%4];" \
        : "=r"((r)[0]), "=r"((r)[1]), "=r"((r)[2]), "=r"((r)[3]) : "r"(addr))
#define MMA_OP(d, a, b0, b1) \
    asm volatile("mma.sync.aligned.m16n8k16.row.col.f32.f16.f16.f32 " \
        "{%0,%1,%2,%3}, {%4,%5,%6,%7}, {%8,%9}, {%0,%1,%2,%3};" \
        : "+f"((d)[0]), "+f"((d)[1]), "+f"((d)[2]), "+f"((d)[3]) \
        : "r"((a)[0]), "r"((a)[1]), "r"((a)[2]), "r"((a)[3]), "r"(b0), "r"(b1))
#define CP16(dst, src) \
    asm volatile("cp.async.cg.shared.global [%0], [%1], 16;" :: "r"(dst), "l"(src))
#define CPCOMMIT() asm volatile("cp.async.commit_group;" ::: "memory")
#define CPWAIT0()  asm volatile("cp.async.wait_group 0;" ::: "memory")
#define CPWAIT1()  asm volatile("cp.async.wait_group 1;" ::: "memory")

// ---- fused_s12 SMEM layout (256 threads, 64 rows/block) ----
#define FA_OFF 0u
#define FB_OFF 8192u
#define FSTAGE 40960u                  // A 8K + B 32K
#define H1F_OFF (2u * FSTAGE)          // 81920: h1 tile 64x256, 4 chunks x 8KB
#define SMEM_FUSED (H1F_OFF + 32768u)  // 114688

// ---- hmma_s3 SMEM layout (256 threads, 128x128 tile, 3-stage) ----
#define SA_OFF 0u
#define SB_OFF 16384u
#define SSTAGE 32768u                  // A 16K + B 16K
#define SMEM_S3 (3u * SSTAGE)          // 98304

// ---------------------------------------------------------------------------
// conv_all (down_W + expert_W only; up_W converted inside fused_s12) + id prep.
// ---------------------------------------------------------------------------
__global__ void conv_all(const float* __restrict__ dw, __half* __restrict__ DW,
                         const float* __restrict__ ew, __half* __restrict__ EW,
                         const int* __restrict__ dom) {
    if (blockIdx.x == 0 && threadIdx.x == 0) {
        bool is64 = true;
        for (int k = 0; k < 16; k++) {
            int hi = dom[2 * k + 1];
            if (hi != 0 && hi != -1) { is64 = false; break; }
        }
        for (int b = 0; b < Bv; b++) {
            long long v;
            if (is64) {
                unsigned int lo = (unsigned int)dom[2 * b];
                int hi = dom[2 * b + 1];
                v = ((long long)hi << 32) | (long long)lo;
            } else {
                v = dom[b];
            }
            g_valid[b] = (v >= 0 && v < Ev) ? 1 : 0;
            long long c = v < 0 ? 0 : (v > (Ev - 1) ? (Ev - 1) : v);
            g_idx[b] = (int)c;
        }
    }
    const int n_dw = Av * Dv / 4, n_ew = Ev * Av * Av / 4;
    const int total = n_dw + n_ew;
    for (int i = blockIdx.x * blockDim.x + threadIdx.x; i < total;
         i += gridDim.x * blockDim.x) {
        const float* src;
        __half* dst;
        int j = i;
        if (j < n_dw) { src = dw; dst = DW; }
        else { j -= n_dw; src = ew; dst = EW; }
        float4 v = ((const float4*)src)[j];
        __half2 h0 = __floats2half2_rn(v.x, v.y);
        __half2 h1 = __floats2half2_rn(v.z, v.w);
        ((uint2*)dst)[j] = make_uint2(*(uint32_t*)&h0, *(uint32_t*)&h1);
    }
}

__device__ __forceinline__ float gelu_exact(float v) {
    return 0.5f * v * (1.0f + erff(v * 0.70710678118654752440f));
}

__device__ __forceinline__ void conv_store(char* base, uint32_t off, float4 v) {
    __half2 h0 = __floats2half2_rn(v.x, v.y);
    __half2 h1 = __floats2half2_rn(v.z, v.w);
    *(uint2*)(base + off) = make_uint2(*(uint32_t*)&h0, *(uint32_t*)&h1);
}

// cp.async loaders into swizzled SMEM (256 threads).
template <int ROWS>
__device__ __forceinline__ void load_t(uint32_t dst,
                                       const __half* __restrict__ hi,
                                       int tid, int K, int k0) {
#pragma unroll
    for (int i = 0; i < ROWS / 32; i++) {
        const int idx = tid + i * 256;
        const int row = idx >> 3;
        const int c8 = idx & 7;
        const uint32_t off = (uint32_t)(row * 128) +
                             (uint32_t)((c8 * 16) ^ ((row & 7) << 4));
        CP16(dst + off, hi + (size_t)row * K + k0 + c8 * 8);
    }
}

// Warp-tile compute step (warp tile 32x64: mt 2, nt 8).
__device__ __forceinline__ void k16_step(uint32_t aBase, uint32_t bBase,
                                         int wm, int wn, int lane, int k16,
                                         float acc[2][8][4]) {
    uint32_t ah[2][4], bh[4][4];
#pragma unroll
    for (int mt = 0; mt < 2; mt++) {
        const int row = wm * 32 + mt * 16 + (lane & 15);
        const int kc  = k16 * 16 + (lane >> 4) * 8;
        const uint32_t off = (uint32_t)(row * 128) +
                             (uint32_t)((kc * 2) ^ ((row & 7) << 4));
        LDSM4(ah[mt], aBase + off);
    }
#pragma unroll
    for (int p = 0; p < 4; p++) {
        const int g    = lane >> 3;
        const int nrow = wn * 64 + p * 16 + (g >> 1) * 8 + (lane & 7);
        const int kc   = k16 * 16 + (g & 1) * 8;
        const uint32_t off = (uint32_t)(nrow * 128) +
                             (uint32_t)((kc * 2) ^ ((nrow & 7) << 4));
        LDSM4(bh[p], bBase + off);
    }
#pragma unroll
    for (int mt = 0; mt < 2; mt++)
#pragma unroll
        for (int nt = 0; nt < 8; nt++) {
            const int p = nt >> 1;
            const int q = (nt & 1) * 2;
            MMA_OP(acc[mt][nt], ah[mt], bh[p][q], bh[p][q + 1]);
        }
}

// h1 SMEM tile address (64-row chunks of 8KB): chunk = col/64.
__device__ __forceinline__ uint32_t h1f_off(int rl, int col) {
    return H1F_OFF + (uint32_t)((col >> 6) * 8192) + (uint32_t)(rl * 128) +
           (uint32_t)(((col & 63) * 2) ^ ((rl & 7) << 4));
}

// ---------------------------------------------------------------------------
// Fused stages 1+2: block = 64 rows x A=256, 256 threads (8 warps 2Mx4N).
// Also converts a 512-elem slice of up_W (hidden under prologue latency).
// GEMM2's expert-B chunk 0 is prefetched during GEMM1's last chunk.
// ---------------------------------------------------------------------------
__global__ __launch_bounds__(256, 2)
void fused_s12(const float* __restrict__ Afp,
               const float* __restrict__ down_b,
               const float* __restrict__ expert_b,
               const float* __restrict__ domain_emb,
               const float* __restrict__ up_W) {
    constexpr int K1 = Dv;
    constexpr int NC1 = K1 / 64;

    extern __shared__ char sm[];
    const uint32_t sbase = smem_u32(sm);

    const int tid  = threadIdx.x;
    const int lane = tid & 31;
    const int wid  = tid >> 5;
    const int wm   = wid & 1;
    const int wn   = wid >> 1;

    const int m0 = blockIdx.y * 64;
    const int b  = m0 >> 10;
    const int e  = g_idx[b];
    const int valid = g_valid[b];

    const float* ArowF = Afp + (size_t)m0 * K1;
    const __half* Brow2 = g_ewh + (size_t)e * Av * Av;
    const float* biasp = expert_b + (size_t)e * Av;
    const float* embp  = domain_emb + (size_t)e * Av;

    int lr[4], lc[4];
    uint32_t soff[4];
    float4 pA[4];
#pragma unroll
    for (int i = 0; i < 4; i++) {
        const int idx = tid + i * 256;
        lr[i] = idx >> 4;
        lc[i] = (idx & 15) * 4;
        soff[i] = (uint32_t)(lr[i] * 128) +
                  (uint32_t)((lc[i] * 2) ^ ((lr[i] & 7) << 4));
        pA[i] = *(const float4*)(ArowF + (size_t)lr[i] * K1 + lc[i]);
    }

    load_t<256>(sbase + FB_OFF, g_dwh, tid, K1, 0);
    CPCOMMIT();

    // Convert this block's slice of up_W (512 elems = 128 float4) -> g_uwh.
    // Hidden under prologue cp.async latency; s3 consumes after kernel boundary.
    {
        const int base4 = blockIdx.y * 128;   // float4 units; 512 blocks x 128 = 64Ki
        if (tid < 128) {
            const int j = base4 + tid;
            float4 v = ((const float4*)up_W)[j];
            __half2 h0 = __floats2half2_rn(v.x, v.y);
            __half2 h1 = __floats2half2_rn(v.z, v.w);
            ((uint2*)g_uwh)[j] = make_uint2(*(uint32_t*)&h0, *(uint32_t*)&h1);
        }
    }

    float acc[2][8][4];
#pragma unroll
    for (int mt = 0; mt < 2; mt++)
#pragma unroll
        for (int nt = 0; nt < 8; nt++)
#pragma unroll
            for (int q = 0; q < 4; q++) acc[mt][nt][q] = 0.f;

    // GEMM1 (K=1024) — single sync per chunk
    for (int c = 0; c < NC1; c++) {
        const int s = c & 1;
        const uint32_t sb = sbase + s * FSTAGE;
        char* smc = sm + s * FSTAGE;
#pragma unroll
        for (int i = 0; i < 4; i++)
            conv_store(smc + FA_OFF, soff[i], pA[i]);
        CPWAIT0();
        __syncthreads();

        if (c + 1 < NC1) {
            load_t<256>(sbase + ((s ^ 1) * FSTAGE) + FB_OFF, g_dwh, tid, K1, (c + 1) * 64);
            CPCOMMIT();
#pragma unroll
            for (int i = 0; i < 4; i++)
                pA[i] = *(const float4*)(ArowF + (size_t)lr[i] * K1 + (c + 1) * 64 + lc[i]);
        } else {
            // prefetch GEMM2 chunk 0 (expert_W) into stage 0 B region;
            // stage 0's last reader (chunk NC1-2 compute) finished before this sync.
            load_t<256>(sbase + FB_OFF, Brow2, tid, Av, 0);
            CPCOMMIT();
        }
#pragma unroll
        for (int k16 = 0; k16 < 4; k16++)
            k16_step(sb + FA_OFF, sb + FB_OFF, wm, wn, lane, k16, acc);
    }

    // epilogue 1: bias + GELU -> h1 in SMEM (H1 region disjoint from stages;
    // acc is register-private, so no barrier needed before the writes).
#pragma unroll
    for (int mt = 0; mt < 2; mt++)
#pragma unroll
        for (int half = 0; half < 2; half++) {
            const int rl = wm * 32 + mt * 16 + (lane >> 2) + half * 8;
#pragma unroll
            for (int nt = 0; nt < 8; nt++) {
                const int col = wn * 64 + nt * 8 + (lane & 3) * 2;
                const float2 bi = *(const float2*)(down_b + col);
                float vx = gelu_exact(acc[mt][nt][half * 2] + bi.x);
                float vy = gelu_exact(acc[mt][nt][half * 2 + 1] + bi.y);
                __half2 h = __floats2half2_rn(vx, vy);
                *(uint32_t*)(sm + h1f_off(rl, col)) = *(uint32_t*)&h;
            }
        }
    __syncthreads();

    // GEMM2 (K=256, A = h1 in SMEM); chunk 0 already in flight.
#pragma unroll
    for (int mt = 0; mt < 2; mt++)
#pragma unroll
        for (int nt = 0; nt < 8; nt++)
#pragma unroll
            for (int q = 0; q < 4; q++) acc[mt][nt][q] = 0.f;

    for (int c = 0; c < 4; c++) {
        const int s = c & 1;
        const uint32_t sb = sbase + s * FSTAGE;
        CPWAIT0();
        __syncthreads();
        if (c + 1 < 4) {
            load_t<256>(sbase + ((s ^ 1) * FSTAGE) + FB_OFF, Brow2, tid, Av, (c + 1) * 64);
            CPCOMMIT();
        }
#pragma unroll
        for (int k16 = 0; k16 < 4; k16++)
            k16_step(sbase + H1F_OFF + (uint32_t)(c * 8192), sb + FB_OFF,
                     wm, wn, lane, k16, acc);
    }

    // epilogue 2: (+b_e or passthrough) + emb -> g_h2 fp16
#pragma unroll
    for (int mt = 0; mt < 2; mt++)
#pragma unroll
        for (int half = 0; half < 2; half++) {
            const int rl = wm * 32 + mt * 16 + (lane >> 2) + half * 8;
            const int r  = m0 + rl;
#pragma unroll
            for (int nt = 0; nt < 8; nt++) {
                const int col = wn * 64 + nt * 8 + (lane & 3) * 2;
                float vx, vy;
                if (valid) {
                    const float2 bi = *(const float2*)(biasp + col);
                    vx = acc[mt][nt][half * 2] + bi.x;
                    vy = acc[mt][nt][half * 2 + 1] + bi.y;
                } else {
                    uint32_t ph = *(uint32_t*)(sm + h1f_off(rl, col));
                    float2 fh = __half22float2(*(__half2*)&ph);
                    vx = fh.x; vy = fh.y;
                }
                const float2 em = *(const float2*)(embp + col);
                vx += em.x; vy += em.y;
                __half2 h = __floats2half2_rn(vx, vy);
                *(uint32_t*)(g_h2 + (size_t)r * Av + col) = *(uint32_t*)&h;
            }
        }
}

// ---------------------------------------------------------------------------
// Stage 3: U = h2 * up_W^T + up_b -> g_uo fp16.
// 128x128 tile, 256 threads (8 warps 4Mx2N), 3-stage ring, 2 CTAs/SM.
// ---------------------------------------------------------------------------
__global__ __launch_bounds__(256, 2)
void hmma_s3(const float* __restrict__ bias) {
    constexpr int K = Av;
    constexpr int NC = K / 64;

    extern __shared__ char sm[];
    const uint32_t sbase = smem_u32(sm);

    const int tid  = threadIdx.x;
    const int lane = tid & 31;
    const int wid  = tid >> 5;
    const int wm   = wid & 3;
    const int wn   = wid >> 2;

    const int m0 = blockIdx.y * 128;
    const int n0 = blockIdx.x * 128;
    const __half* ArowH = g_h2 + (size_t)m0 * K;
    const __half* BrowH = g_uwh + (size_t)n0 * K;

    load_t<128>(sbase + SA_OFF, ArowH, tid, K, 0);
    load_t<128>(sbase + SB_OFF, BrowH, tid, K, 0);
    CPCOMMIT();
    load_t<128>(sbase + SSTAGE + SA_OFF, ArowH, tid, K, 64);
    load_t<128>(sbase + SSTAGE + SB_OFF, BrowH, tid, K, 64);
    CPCOMMIT();

    float acc[2][8][4];
#pragma unroll
    for (int mt = 0; mt < 2; mt++)
#pragma unroll
        for (int nt = 0; nt < 8; nt++)
#pragma unroll
            for (int q = 0; q < 4; q++) acc[mt][nt][q] = 0.f;

#pragma unroll
    for (int c = 0; c < NC; c++) {
        if (c < NC - 1) { CPWAIT1(); } else { CPWAIT0(); }
        __syncthreads();
        if (c + 2 < NC) {
            const uint32_t nb = sbase + ((c + 2) % 3) * SSTAGE;
            load_t<128>(nb + SA_OFF, ArowH, tid, K, (c + 2) * 64);
            load_t<128>(nb + SB_OFF, BrowH, tid, K, (c + 2) * 64);
            CPCOMMIT();
        }
        const uint32_t sb = sbase + (c % 3) * SSTAGE;
#pragma unroll
        for (int k16 = 0; k16 < 4; k16++)
            k16_step(sb + SA_OFF, sb + SB_OFF, wm, wn, lane, k16, acc);
    }

#pragma unroll
    for (int mt = 0; mt < 2; mt++)
#pragma unroll
        for (int half = 0; half < 2; half++) {
            const int r = m0 + wm * 32 + mt * 16 + (lane >> 2) + half * 8;
#pragma unroll
            for (int nt = 0; nt < 8; nt++) {
                const int col = n0 + wn * 64 + nt * 8 + (lane & 3) * 2;
                const float2 bi = *(const float2*)(bias + col);
                float vx = acc[mt][nt][half * 2] + bi.x;
                float vy = acc[mt][nt][half * 2 + 1] + bi.y;
                __half2 h = __floats2half2_rn(vx, vy);
                *(uint32_t*)(g_uo + (size_t)r * Dv + col) = *(uint32_t*)&h;
            }
        }
}

// ---------------------------------------------------------------------------
// LayerNorm: 128 threads/row, 8 elems/thread, coalesced.
// ---------------------------------------------------------------------------
__global__ __launch_bounds__(128)
void ln_kernel(const float* __restrict__ residual,
               const float* __restrict__ gamma,
               const float* __restrict__ beta,
               float* __restrict__ out) {
    const int row = blockIdx.x;
    const int t = threadIdx.x;
    const int c0 = t * 8;

    const uint4 uh = *(const uint4*)(g_uo + (size_t)row * Dv + c0);
    const float4 r0 = __ldcs((const float4*)(residual + (size_t)row * Dv + c0));
    const float4 r1 = __ldcs((const float4*)(residual + (size_t)row * Dv + c0 + 4));

    float v[8];
    {
        float2 a = __half22float2(*(const __half2*)&uh.x);
        float2 b = __half22float2(*(const __half2*)&uh.y);
        float2 c = __half22float2(*(const __half2*)&uh.z);
        float2 d = __half22float2(*(const __half2*)&uh.w);
        v[0] = a.x + r0.x; v[1] = a.y + r0.y;
        v[2] = b.x + r0.z; v[3] = b.y + r0.w;
        v[4] = c.x + r1.x; v[5] = c.y + r1.y;
        v[6] = d.x + r1.z; v[7] = d.y + r1.w;
    }

    __shared__ float red1[4];
    __shared__ float red2[4];

    float s = 0.f;
#pragma unroll
    for (int i = 0; i < 8; i++) s += v[i];
#pragma unroll
    for (int o = 16; o; o >>= 1) s += __shfl_xor_sync(0xFFFFFFFFu, s, o);
    if ((t & 31) == 0) red1[t >> 5] = s;
    __syncthreads();
    const float mu = (red1[0] + red1[1] + red1[2] + red1[3]) * (1.0f / Dv);

    float s2 = 0.f;
#pragma unroll
    for (int i = 0; i < 8; i++) {
        v[i] -= mu;
        s2 += v[i] * v[i];
    }
#pragma unroll
    for (int o = 16; o; o >>= 1) s2 += __shfl_xor_sync(0xFFFFFFFFu, s2, o);
    if ((t & 31) == 0) red2[t >> 5] = s2;
    __syncthreads();
    const float inv = rsqrtf((red2[0] + red2[1] + red2[2] + red2[3]) * (1.0f / Dv) + 1e-5f);

    const float4 gm0 = *(const float4*)(gamma + c0);
    const float4 gm1 = *(const float4*)(gamma + c0 + 4);
    const float4 bt0 = *(const float4*)(beta + c0);
    const float4 bt1 = *(const float4*)(beta + c0 + 4);
    float4 o0, o1;
    o0.x = v[0] * inv * gm0.x + bt0.x;
    o0.y = v[1] * inv * gm0.y + bt0.y;
    o0.z = v[2] * inv * gm0.z + bt0.z;
    o0.w = v[3] * inv * gm0.w + bt0.w;
    o1.x = v[4] * inv * gm1.x + bt1.x;
    o1.y = v[5] * inv * gm1.y + bt1.y;
    o1.z = v[6] * inv * gm1.z + bt1.z;
    o1.w = v[7] * inv * gm1.w + bt1.w;
    __stcs((float4*)(out + (size_t)row * Dv + c0), o0);
    __stcs((float4*)(out + (size_t)row * Dv + c0 + 4), o1);
}

// ---------------------------------------------------------------------------
extern "C" void kernel_launch(void* const* d_in, const int* in_sizes, int n_in,
                              void* d_out, int out_size) {
    const float* hidden     = (const float*)d_in[0];
    const int*   dom        = (const int*)d_in[1];
    const float* down_W     = (const float*)d_in[2];
    const float* down_b     = (const float*)d_in[3];
    const float* up_W       = (const float*)d_in[4];
    const float* up_b       = (const float*)d_in[5];
    const float* expert_W   = (const float*)d_in[6];
    const float* expert_b   = (const float*)d_in[7];
    const float* domain_emb = (const float*)d_in[8];
    const float* gamma      = (const float*)d_in[9];
    const float* beta       = (const float*)d_in[10];
    float* out = (float*)d_out;

    cudaFuncSetAttribute(fused_s12, cudaFuncAttributeMaxDynamicSharedMemorySize, SMEM_FUSED);
    cudaFuncSetAttribute(hmma_s3, cudaFuncAttributeMaxDynamicSharedMemorySize, SMEM_S3);

    __half *dwh, *ewh;
    cudaGetSymbolAddress((void**)&dwh, g_dwh);
    cudaGetSymbolAddress((void**)&ewh, g_ewh);
    conv_all<<<512, 512>>>(down_W, dwh, expert_W, ewh, dom);

    // Stages 1+2 fused (64 rows/block, 2 CTAs/SM); also converts up_W slices.
    fused_s12<<<dim3(1, Mrows / 64), 256, SMEM_FUSED>>>(hidden, down_b, expert_b,
                                                        domain_emb, up_W);
    // Stage 3 (128x128 blocks, 2 CTAs/SM, 3-stage ring)
    hmma_s3<<<dim3(Dv / 128, Mrows / 128), 256, SMEM_S3>>>(up_b);
    // Residual + LayerNorm (coalesced, 128 thr/row)
    ln_kernel<<<Mrows, 128>>>(hidden, gamma, beta, out);
}